// round 7
// baseline (speedup 1.0000x reference)
#include <cuda_runtime.h>
#include <cstdint>

#define NN 100000
#define NE 1600000
#define D  128
#define SCAN_CHUNK 2048
#define SCAN_NBLK ((NN + SCAN_CHUNK - 1) / SCAN_CHUNK)   // 49

// ---------------- scratch: __device__ globals only (no allocations) ----------------
__device__ int   g_is64;
__device__ int   g_deg[NN];
__device__ int   g_off[NN];
__device__ int   g_cursor[NN];
__device__ int   g_bsum[SCAN_NBLK];
__device__ int   g_srcs[NE];
__device__ float g_h[(size_t)NN * D];   // aggregated+normalized features (GEMM input)

// ---------------- packed f32x2 helpers ----------------
__device__ __forceinline__ uint64_t pack2(float lo, float hi) {
    uint64_t r;
    asm("mov.b64 %0, {%1, %2};" : "=l"(r) : "f"(lo), "f"(hi));
    return r;
}
__device__ __forceinline__ void unpack2(uint64_t v, float& lo, float& hi) {
    asm("mov.b64 {%0, %1}, %2;" : "=f"(lo), "=f"(hi) : "l"(v));
}
__device__ __forceinline__ void ffma2(uint64_t& d, uint64_t a, uint64_t b) {
    asm("fma.rn.f32x2 %0, %1, %2, %0;" : "+l"(d) : "l"(a), "l"(b));
}

// ---------------- dtype detection: int64 vs int32 edge buffer ----------------
__global__ void detect_kernel(const int* __restrict__ ei32) {
    if (blockIdx.x == 0 && threadIdx.x == 0) {
        int nz = 0;
        #pragma unroll 8
        for (int i = 0; i < 512; i++) nz |= ei32[2 * i + 1];
        g_is64 = (nz == 0) ? 1 : 0;
    }
}

// ---------------- CSR build ----------------
__global__ void zero_deg_kernel(int n) {
    int i = blockIdx.x * blockDim.x + threadIdx.x;
    if (i < n) g_deg[i] = 0;
}

__device__ __forceinline__ int load_idx(const int* __restrict__ ei32,
                                        int is64, size_t pos) {
    return is64 ? ei32[2 * pos] : ei32[pos];
}

__global__ void count_kernel(const int* __restrict__ ei32, int E) {
    int e = blockIdx.x * blockDim.x + threadIdx.x;
    if (e < E) {
        int dst = load_idx(ei32, g_is64, (size_t)E + e);
        if ((unsigned)dst < (unsigned)NN)
            atomicAdd(&g_deg[dst], 1);
    }
}

__global__ __launch_bounds__(1024)
void scan_local_kernel(int n) {
    __shared__ int wsum[32];
    int t = threadIdx.x, lane = t & 31, w = t >> 5;
    int base = blockIdx.x * SCAN_CHUNK;
    int i0 = base + 2 * t, i1 = i0 + 1;
    int v0 = (i0 < n) ? g_deg[i0] : 0;
    int v1 = (i1 < n) ? g_deg[i1] : 0;
    int s = v0 + v1;
    int inc = s;
    #pragma unroll
    for (int d = 1; d < 32; d <<= 1) {
        int nb = __shfl_up_sync(0xffffffffu, inc, d);
        if (lane >= d) inc += nb;
    }
    if (lane == 31) wsum[w] = inc;
    __syncthreads();
    if (w == 0) {
        int x = wsum[lane];
        #pragma unroll
        for (int d = 1; d < 32; d <<= 1) {
            int nb = __shfl_up_sync(0xffffffffu, x, d);
            if (lane >= d) x += nb;
        }
        wsum[lane] = x;
    }
    __syncthreads();
    int woff = (w == 0) ? 0 : wsum[w - 1];
    int exc = woff + inc - s;                 // exclusive prefix within block
    if (i0 < n) g_off[i0] = exc;
    if (i1 < n) g_off[i1] = exc + v0;
    if (t == 1023) g_bsum[blockIdx.x] = wsum[31];   // single writer
}

__global__ void scan_bsum_kernel(int nb) {
    int lane = threadIdx.x;                   // 32 threads
    int v0 = (lane < nb) ? g_bsum[lane] : 0;
    int v1 = (lane + 32 < nb) ? g_bsum[lane + 32] : 0;
    int s0 = v0;
    #pragma unroll
    for (int d = 1; d < 32; d <<= 1) {
        int nb_ = __shfl_up_sync(0xffffffffu, s0, d);
        if (lane >= d) s0 += nb_;
    }
    int tot0 = __shfl_sync(0xffffffffu, s0, 31);
    int s1 = v1;
    #pragma unroll
    for (int d = 1; d < 32; d <<= 1) {
        int nb_ = __shfl_up_sync(0xffffffffu, s1, d);
        if (lane >= d) s1 += nb_;
    }
    s1 += tot0;
    if (lane < nb)      g_bsum[lane]      = s0 - v0;   // exclusive
    if (lane + 32 < nb) g_bsum[lane + 32] = s1 - v1;
}

__global__ __launch_bounds__(1024)
void scan_add_kernel(int n) {
    int add = g_bsum[blockIdx.x];
    int base = blockIdx.x * SCAN_CHUNK;
    int i0 = base + 2 * threadIdx.x, i1 = i0 + 1;
    if (i0 < n) { int o = g_off[i0] + add; g_off[i0] = o; g_cursor[i0] = o; }
    if (i1 < n) { int o = g_off[i1] + add; g_off[i1] = o; g_cursor[i1] = o; }
}

__global__ void fill_kernel(const int* __restrict__ ei32, int E) {
    int e = blockIdx.x * blockDim.x + threadIdx.x;
    if (e < E) {
        int is64 = g_is64;
        int src = load_idx(ei32, is64, (size_t)e);
        int dst = load_idx(ei32, is64, (size_t)E + e);
        if ((unsigned)dst < (unsigned)NN && (unsigned)src < (unsigned)NN) {
            int pos = atomicAdd(&g_cursor[dst], 1);
            if ((unsigned)pos < (unsigned)NE)
                g_srcs[pos] = src;
        }
    }
}

// ---------------- aggregation: warp per node, no float atomics ----------------
__global__ void aggregate_kernel(const float* __restrict__ X, int n) {
    int node = blockIdx.x * (blockDim.x >> 5) + (threadIdx.x >> 5);
    int lane = threadIdx.x & 31;
    if (node >= n) return;
    int start = g_off[node];
    int cnt   = g_deg[node];
    const float4* X4 = (const float4*)X;

    float4 acc = make_float4(0.f, 0.f, 0.f, 0.f);
    int e = 0;
    for (; e + 4 <= cnt; e += 4) {
        int s0 = g_srcs[start + e + 0];
        int s1 = g_srcs[start + e + 1];
        int s2 = g_srcs[start + e + 2];
        int s3 = g_srcs[start + e + 3];
        float4 v0 = __ldg(X4 + (size_t)s0 * 32 + lane);
        float4 v1 = __ldg(X4 + (size_t)s1 * 32 + lane);
        float4 v2 = __ldg(X4 + (size_t)s2 * 32 + lane);
        float4 v3 = __ldg(X4 + (size_t)s3 * 32 + lane);
        acc.x += v0.x + v1.x + v2.x + v3.x;
        acc.y += v0.y + v1.y + v2.y + v3.y;
        acc.z += v0.z + v1.z + v2.z + v3.z;
        acc.w += v0.w + v1.w + v2.w + v3.w;
    }
    for (; e < cnt; e++) {
        int s = g_srcs[start + e];
        float4 v = __ldg(X4 + (size_t)s * 32 + lane);
        acc.x += v.x; acc.y += v.y; acc.z += v.z; acc.w += v.w;
    }
    float4 self = __ldg(X4 + (size_t)node * 32 + lane);
    float inv = 1.0f / (float)(cnt + 1);
    float4 h;
    h.x = (acc.x + self.x) * inv;
    h.y = (acc.y + self.y) * inv;
    h.z = (acc.z + self.z) * inv;
    h.w = (acc.w + self.w) * inv;
    ((float4*)g_h)[(size_t)node * 32 + lane] = h;
}

// ---------------- GEMM (M x 128) @ (128 x 128) + bias + leaky relu ----------------
// 256 threads, 128-row tile, 8x8 microtile via packed f32x2 FMA (FFMA2).
#define LDP 132

__global__ __launch_bounds__(256)
void gemm_bias_lrelu_kernel(const float* __restrict__ W,
                            const float* __restrict__ bias,
                            float* __restrict__ Out, int M) {
    extern __shared__ float smem[];
    float* Ast = smem;              // [128][LDP]  A transposed: Ast[k][r]
    float* Ws  = smem + 128 * LDP;  // [128][LDP]  Ws[k][c]

    int block_row = blockIdx.x * 128;
    int rows = M - block_row; if (rows > 128) rows = 128;
    int t = threadIdx.x;

    const float* A = g_h;

    for (int i = t; i < 128 * 32; i += 256) {
        int k = i >> 5, c4 = i & 31;
        float4 v = ((const float4*)W)[i];
        *(float4*)(Ws + k * LDP + c4 * 4) = v;
    }
    for (int i = t; i < 128 * 32; i += 256) {
        int r = i >> 5, c4 = i & 31;
        float4 v = make_float4(0.f, 0.f, 0.f, 0.f);
        if (r < rows)
            v = ((const float4*)(A + (size_t)(block_row + r) * D))[c4];
        Ast[(c4 * 4 + 0) * LDP + r] = v.x;
        Ast[(c4 * 4 + 1) * LDP + r] = v.y;
        Ast[(c4 * 4 + 2) * LDP + r] = v.z;
        Ast[(c4 * 4 + 3) * LDP + r] = v.w;
    }
    __syncthreads();

    int tx = t & 15, ty = t >> 4;
    int c0 = tx * 8, r0 = ty * 8;

    // 8 rows x 4 column-pairs of packed f32x2 accumulators
    uint64_t acc2[8][4];
    #pragma unroll
    for (int i = 0; i < 8; i++)
        #pragma unroll
        for (int j = 0; j < 4; j++) acc2[i][j] = 0ull;

    #pragma unroll 4
    for (int k = 0; k < 128; k++) {
        float4 a0 = *(const float4*)(Ast + k * LDP + r0);
        float4 a1 = *(const float4*)(Ast + k * LDP + r0 + 4);
        float4 w0 = *(const float4*)(Ws  + k * LDP + c0);
        float4 w1 = *(const float4*)(Ws  + k * LDP + c0 + 4);
        uint64_t w2[4];
        w2[0] = pack2(w0.x, w0.y);
        w2[1] = pack2(w0.z, w0.w);
        w2[2] = pack2(w1.x, w1.y);
        w2[3] = pack2(w1.z, w1.w);
        float a[8] = {a0.x, a0.y, a0.z, a0.w, a1.x, a1.y, a1.z, a1.w};
        #pragma unroll
        for (int i = 0; i < 8; i++) {
            uint64_t a2 = pack2(a[i], a[i]);
            #pragma unroll
            for (int j = 0; j < 4; j++)
                ffma2(acc2[i][j], a2, w2[j]);
        }
    }

    float bv[8];
    #pragma unroll
    for (int j = 0; j < 8; j++) bv[j] = bias[c0 + j];

    #pragma unroll
    for (int i = 0; i < 8; i++) {
        int r = r0 + i;
        if (r < rows) {
            float o[8];
            #pragma unroll
            for (int j = 0; j < 4; j++) {
                float lo, hi;
                unpack2(acc2[i][j], lo, hi);
                float v0 = lo + bv[2 * j];
                float v1 = hi + bv[2 * j + 1];
                o[2 * j]     = (v0 >= 0.f) ? v0 : 0.01f * v0;
                o[2 * j + 1] = (v1 >= 0.f) ? v1 : 0.01f * v1;
            }
            float* dst = Out + (size_t)(block_row + r) * D + c0;
            *(float4*)(dst)     = make_float4(o[0], o[1], o[2], o[3]);
            *(float4*)(dst + 4) = make_float4(o[4], o[5], o[6], o[7]);
        }
    }
}

// ---------------- launch ----------------
extern "C" void kernel_launch(void* const* d_in, const int* in_sizes, int n_in,
                              void* d_out, int out_size) {
    const float* feat = (const float*)d_in[0];
    const int*   ei32 = (const int*)d_in[1];   // int32 OR int64 (auto-detected)
    const float* W1   = (const float*)d_in[2];
    const float* b1   = (const float*)d_in[3];
    const float* W2   = (const float*)d_in[4];
    const float* b2   = (const float*)d_in[5];
    float* out = (float*)d_out;

    int N = in_sizes[0] / D;      // 100000
    int E = in_sizes[1] / 2;      // 1600000

    const size_t gemm_smem = (size_t)2 * 128 * LDP * sizeof(float);
    cudaFuncSetAttribute(gemm_bias_lrelu_kernel,
                         cudaFuncAttributeMaxDynamicSharedMemorySize,
                         (int)gemm_smem);

    // dtype detection + CSR build (shared by both layers)
    detect_kernel<<<1, 32>>>(ei32);
    zero_deg_kernel<<<(N + 255) / 256, 256>>>(N);
    count_kernel<<<(E + 255) / 256, 256>>>(ei32, E);
    scan_local_kernel<<<SCAN_NBLK, 1024>>>(N);
    scan_bsum_kernel<<<1, 32>>>(SCAN_NBLK);
    scan_add_kernel<<<SCAN_NBLK, 1024>>>(N);
    fill_kernel<<<(E + 255) / 256, 256>>>(ei32, E);

    int agg_blocks  = (N + 7) / 8;            // 8 warps per 256-thread block
    int gemm_blocks = (N + 127) / 128;

    // layer 1
    aggregate_kernel<<<agg_blocks, 256>>>(feat, N);
    gemm_bias_lrelu_kernel<<<gemm_blocks, 256, gemm_smem>>>(W1, b1, out, N);
    // layer 2
    aggregate_kernel<<<agg_blocks, 256>>>(out, N);
    gemm_bias_lrelu_kernel<<<gemm_blocks, 256, gemm_smem>>>(W2, b2, out, N);
}

// round 8
// speedup vs baseline: 1.6751x; 1.6751x over previous
#include <cuda_runtime.h>
#include <cuda_bf16.h>
#include <cstdint>

#define NN 100000
#define NE 1600000
#define D  128
#define SCAN_CHUNK 2048
#define SCAN_NBLK ((NN + SCAN_CHUNK - 1) / SCAN_CHUNK)   // 49

// ---------------- scratch: __device__ globals only ----------------
__device__ int   g_is64;
__device__ int   g_deg[NN];
__device__ int   g_off[NN];
__device__ int   g_cursor[NN];
__device__ int   g_bsum[SCAN_NBLK];
__device__ int   g_srcs[NE];
__device__ __nv_bfloat16 g_ahi[(size_t)NN * D];   // aggregated feats, bf16 hi
__device__ __nv_bfloat16 g_alo[(size_t)NN * D];   // bf16 lo residual
__device__ __nv_bfloat16 g_bhi[D * D];            // W^T hi  [n][k]
__device__ __nv_bfloat16 g_blo[D * D];            // W^T lo  [n][k]

// ---------------- warp-MMA helpers (sm_80+ features, safe on sm_103 target) ----
__device__ __forceinline__ uint32_t smem_u32(const void* p) {
    uint32_t a;
    asm("{ .reg .u64 t; cvta.to.shared.u64 t, %1; cvt.u32.u64 %0, t; }"
        : "=r"(a) : "l"(p));
    return a;
}
__device__ __forceinline__ void ldsm_x4(uint32_t* r, uint32_t addr) {
    asm volatile("ldmatrix.sync.aligned.m8n8.x4.shared.b16 {%0,%1,%2,%3}, [%4];"
                 : "=r"(r[0]), "=r"(r[1]), "=r"(r[2]), "=r"(r[3]) : "r"(addr));
}
__device__ __forceinline__ void mma_bf16(float* c, const uint32_t* a,
                                         const uint32_t* b) {
    asm volatile(
        "mma.sync.aligned.m16n8k16.row.col.f32.bf16.bf16.f32 "
        "{%0,%1,%2,%3}, {%4,%5,%6,%7}, {%8,%9}, {%0,%1,%2,%3};"
        : "+f"(c[0]), "+f"(c[1]), "+f"(c[2]), "+f"(c[3])
        : "r"(a[0]), "r"(a[1]), "r"(a[2]), "r"(a[3]), "r"(b[0]), "r"(b[1]));
}

// ---------------- dtype detection ----------------
__global__ void detect_kernel(const int* __restrict__ ei32) {
    if (blockIdx.x == 0 && threadIdx.x == 0) {
        int nz = 0;
        #pragma unroll 8
        for (int i = 0; i < 512; i++) nz |= ei32[2 * i + 1];
        g_is64 = (nz == 0) ? 1 : 0;
    }
}

// ---------------- CSR build ----------------
__global__ void zero_deg_kernel(int n) {
    int i = blockIdx.x * blockDim.x + threadIdx.x;
    if (i < n) g_deg[i] = 0;
}
__device__ __forceinline__ int load_idx(const int* __restrict__ ei32,
                                        int is64, size_t pos) {
    return is64 ? ei32[2 * pos] : ei32[pos];
}
__global__ void count_kernel(const int* __restrict__ ei32, int E) {
    int e = blockIdx.x * blockDim.x + threadIdx.x;
    if (e < E) {
        int dst = load_idx(ei32, g_is64, (size_t)E + e);
        if ((unsigned)dst < (unsigned)NN) atomicAdd(&g_deg[dst], 1);
    }
}

__global__ __launch_bounds__(1024)
void scan_local_kernel(int n) {
    __shared__ int wsum[32];
    int t = threadIdx.x, lane = t & 31, w = t >> 5;
    int base = blockIdx.x * SCAN_CHUNK;
    int i0 = base + 2 * t, i1 = i0 + 1;
    int v0 = (i0 < n) ? g_deg[i0] : 0;
    int v1 = (i1 < n) ? g_deg[i1] : 0;
    int s = v0 + v1;
    int inc = s;
    #pragma unroll
    for (int d = 1; d < 32; d <<= 1) {
        int nb = __shfl_up_sync(0xffffffffu, inc, d);
        if (lane >= d) inc += nb;
    }
    if (lane == 31) wsum[w] = inc;
    __syncthreads();
    if (w == 0) {
        int x = wsum[lane];
        #pragma unroll
        for (int d = 1; d < 32; d <<= 1) {
            int nb = __shfl_up_sync(0xffffffffu, x, d);
            if (lane >= d) x += nb;
        }
        wsum[lane] = x;
    }
    __syncthreads();
    int woff = (w == 0) ? 0 : wsum[w - 1];
    int exc = woff + inc - s;
    if (i0 < n) g_off[i0] = exc;
    if (i1 < n) g_off[i1] = exc + v0;
    if (t == 1023) g_bsum[blockIdx.x] = wsum[31];   // single writer
}

__global__ void scan_bsum_kernel(int nb) {
    int lane = threadIdx.x;
    int v0 = (lane < nb) ? g_bsum[lane] : 0;
    int v1 = (lane + 32 < nb) ? g_bsum[lane + 32] : 0;
    int s0 = v0;
    #pragma unroll
    for (int d = 1; d < 32; d <<= 1) {
        int nb_ = __shfl_up_sync(0xffffffffu, s0, d);
        if (lane >= d) s0 += nb_;
    }
    int tot0 = __shfl_sync(0xffffffffu, s0, 31);
    int s1 = v1;
    #pragma unroll
    for (int d = 1; d < 32; d <<= 1) {
        int nb_ = __shfl_up_sync(0xffffffffu, s1, d);
        if (lane >= d) s1 += nb_;
    }
    s1 += tot0;
    if (lane < nb)      g_bsum[lane]      = s0 - v0;
    if (lane + 32 < nb) g_bsum[lane + 32] = s1 - v1;
}

__global__ __launch_bounds__(1024)
void scan_add_kernel(int n) {
    int add = g_bsum[blockIdx.x];
    int base = blockIdx.x * SCAN_CHUNK;
    int i0 = base + 2 * threadIdx.x, i1 = i0 + 1;
    if (i0 < n) { int o = g_off[i0] + add; g_off[i0] = o; g_cursor[i0] = o; }
    if (i1 < n) { int o = g_off[i1] + add; g_off[i1] = o; g_cursor[i1] = o; }
}

__global__ void fill_kernel(const int* __restrict__ ei32, int E) {
    int e = blockIdx.x * blockDim.x + threadIdx.x;
    if (e < E) {
        int is64 = g_is64;
        int src = load_idx(ei32, is64, (size_t)e);
        int dst = load_idx(ei32, is64, (size_t)E + e);
        if ((unsigned)dst < (unsigned)NN && (unsigned)src < (unsigned)NN) {
            int pos = atomicAdd(&g_cursor[dst], 1);
            if ((unsigned)pos < (unsigned)NE) g_srcs[pos] = src;
        }
    }
}

// ---------------- aggregation: warp per node -> bf16 hi/lo output ----------------
__global__ void aggregate_kernel(const float* __restrict__ X, int n) {
    int node = blockIdx.x * (blockDim.x >> 5) + (threadIdx.x >> 5);
    int lane = threadIdx.x & 31;
    if (node >= n) return;
    int start = g_off[node];
    int cnt   = g_deg[node];
    const float4* X4 = (const float4*)X;

    float4 acc = make_float4(0.f, 0.f, 0.f, 0.f);
    int e = 0;
    for (; e + 4 <= cnt; e += 4) {
        int s0 = g_srcs[start + e + 0];
        int s1 = g_srcs[start + e + 1];
        int s2 = g_srcs[start + e + 2];
        int s3 = g_srcs[start + e + 3];
        float4 v0 = __ldg(X4 + (size_t)s0 * 32 + lane);
        float4 v1 = __ldg(X4 + (size_t)s1 * 32 + lane);
        float4 v2 = __ldg(X4 + (size_t)s2 * 32 + lane);
        float4 v3 = __ldg(X4 + (size_t)s3 * 32 + lane);
        acc.x += v0.x + v1.x + v2.x + v3.x;
        acc.y += v0.y + v1.y + v2.y + v3.y;
        acc.z += v0.z + v1.z + v2.z + v3.z;
        acc.w += v0.w + v1.w + v2.w + v3.w;
    }
    for (; e < cnt; e++) {
        int s = g_srcs[start + e];
        float4 v = __ldg(X4 + (size_t)s * 32 + lane);
        acc.x += v.x; acc.y += v.y; acc.z += v.z; acc.w += v.w;
    }
    float4 self = __ldg(X4 + (size_t)node * 32 + lane);
    float inv = 1.0f / (float)(cnt + 1);
    float h[4];
    h[0] = (acc.x + self.x) * inv;
    h[1] = (acc.y + self.y) * inv;
    h[2] = (acc.z + self.z) * inv;
    h[3] = (acc.w + self.w) * inv;

    __nv_bfloat16 hi[4], lo[4];
    #pragma unroll
    for (int i = 0; i < 4; i++) {
        hi[i] = __float2bfloat16_rn(h[i]);
        lo[i] = __float2bfloat16_rn(h[i] - __bfloat162float(hi[i]));
    }
    size_t base = (size_t)node * D + lane * 4;
    *(__nv_bfloat162*)(g_ahi + base)     = __nv_bfloat162(hi[0], hi[1]);
    *(__nv_bfloat162*)(g_ahi + base + 2) = __nv_bfloat162(hi[2], hi[3]);
    *(__nv_bfloat162*)(g_alo + base)     = __nv_bfloat162(lo[0], lo[1]);
    *(__nv_bfloat162*)(g_alo + base + 2) = __nv_bfloat162(lo[2], lo[3]);
}

// ---------------- W -> W^T bf16 hi/lo ----------------
__global__ void convert_w_kernel(const float* __restrict__ W) {
    int idx = blockIdx.x * blockDim.x + threadIdx.x;   // 16384 threads
    if (idx >= D * D) return;
    int n = idx >> 7, k = idx & 127;
    float x = W[k * D + n];
    __nv_bfloat16 hi = __float2bfloat16_rn(x);
    __nv_bfloat16 lo = __float2bfloat16_rn(x - __bfloat162float(hi));
    g_bhi[n * D + k] = hi;
    g_blo[n * D + k] = lo;
}

// ---------------- warp-MMA bf16-split GEMM + bias + leaky relu ----------------
// block: 256 threads (8 warps), tile M=128 N=128 K=128.
// warp w: m0 = (w&3)*32, n0 = (w>>2)*64. 3 MMA terms: Ahi*Bhi + Ahi*Blo + Alo*Bhi.
#define ROWB 272                     // padded row: 136 bf16 = 272 B (conflict-free ldsm)
#define SM_BIAS 0
#define SM_AHI  512
#define SM_ALO  (SM_AHI + 128 * ROWB)
#define SM_BHI  (SM_ALO + 128 * ROWB)
#define SM_BLO  (SM_BHI + 128 * ROWB)
#define SM_TOT  (SM_BLO + 128 * ROWB)   // 139776 B

__global__ __launch_bounds__(256)
void gemm_mma_kernel(const float* __restrict__ bias,
                     float* __restrict__ Out, int M) {
    extern __shared__ char smem[];
    uint32_t sb = smem_u32(smem);
    int t = threadIdx.x, lane = t & 31, wid = t >> 5;

    int block_row = blockIdx.x * 128;
    int rows = M - block_row; if (rows > 128) rows = 128;

    // stage bias
    if (t < 32) *(float4*)(smem + SM_BIAS + t * 16) = ((const float4*)bias)[t];

    // stage 4 tiles: row r (128), 16B chunk c (16) -> smem r*ROWB + c*16
    {
        const uint4 z4 = make_uint4(0, 0, 0, 0);
        #pragma unroll
        for (int it = 0; it < 8; it++) {
            int i = t + it * 256;
            int r = i >> 4, c = i & 15;
            uint32_t so = r * ROWB + c * 16;
            size_t g = (size_t)r * 16 + c;           // uint4 index within [n][k] tile
            uint4 va = z4, vl = z4;
            if (r < rows) {
                size_t ga = ((size_t)(block_row + r) * 16) + c;
                va = ((const uint4*)g_ahi)[ga];
                vl = ((const uint4*)g_alo)[ga];
            }
            *(uint4*)(smem + SM_AHI + so) = va;
            *(uint4*)(smem + SM_ALO + so) = vl;
            *(uint4*)(smem + SM_BHI + so) = ((const uint4*)g_bhi)[g];
            *(uint4*)(smem + SM_BLO + so) = ((const uint4*)g_blo)[g];
        }
    }
    __syncthreads();

    int m0 = (wid & 3) * 32;
    int n0 = (wid >> 2) * 64;

    float acc[2][8][4];
    #pragma unroll
    for (int ma = 0; ma < 2; ma++)
        #pragma unroll
        for (int na = 0; na < 8; na++)
            #pragma unroll
            for (int q = 0; q < 4; q++) acc[ma][na][q] = 0.f;

    // per-lane ldmatrix base addresses (k-step adds 32 B)
    // A: matrix quads -> rows l&15, col-half l>>4
    uint32_t aAddr[2];
    #pragma unroll
    for (int ma = 0; ma < 2; ma++) {
        int r = m0 + ma * 16 + (lane & 15);
        aAddr[ma] = sb + SM_AHI + r * ROWB + (lane >> 4) * 16;
    }
    // B: quad q = lane>>3: n-offset ((q&2)<<2) + (l&7), k-offset (q&1)*8
    uint32_t bAddr[4];
    {
        int q = lane >> 3;
        int nrow_off = ((q & 2) << 2) + (lane & 7);
        int kadd = (q & 1) * 8;
        #pragma unroll
        for (int p = 0; p < 4; p++) {
            int nrow = n0 + p * 16 + nrow_off;
            bAddr[p] = sb + SM_BHI + nrow * ROWB + kadd * 2;
        }
    }
    const uint32_t ALO_OFF = SM_ALO - SM_AHI;
    const uint32_t BLO_OFF = SM_BLO - SM_BHI;

    #pragma unroll
    for (int ks = 0; ks < 8; ks++) {
        uint32_t kb = ks * 32;
        uint32_t ahi[2][4], alo[2][4], bhi[8][2], blo[8][2];
        #pragma unroll
        for (int ma = 0; ma < 2; ma++) {
            ldsm_x4(ahi[ma], aAddr[ma] + kb);
            ldsm_x4(alo[ma], aAddr[ma] + ALO_OFF + kb);
        }
        #pragma unroll
        for (int p = 0; p < 4; p++) {
            uint32_t rh[4], rl[4];
            ldsm_x4(rh, bAddr[p] + kb);
            ldsm_x4(rl, bAddr[p] + BLO_OFF + kb);
            bhi[2 * p][0] = rh[0]; bhi[2 * p][1] = rh[1];
            bhi[2 * p + 1][0] = rh[2]; bhi[2 * p + 1][1] = rh[3];
            blo[2 * p][0] = rl[0]; blo[2 * p][1] = rl[1];
            blo[2 * p + 1][0] = rl[2]; blo[2 * p + 1][1] = rl[3];
        }
        #pragma unroll
        for (int ma = 0; ma < 2; ma++)
            #pragma unroll
            for (int na = 0; na < 8; na++) {
                mma_bf16(acc[ma][na], ahi[ma], bhi[na]);
                mma_bf16(acc[ma][na], ahi[ma], blo[na]);
                mma_bf16(acc[ma][na], alo[ma], bhi[na]);
            }
    }

    // epilogue: D frag lane l -> rows l/4 (+8), cols (l%4)*2,+1
    const float* bsm = (const float*)(smem + SM_BIAS);
    int rbase = m0 + (lane >> 2);
    int cpair = (lane & 3) * 2;
    #pragma unroll
    for (int ma = 0; ma < 2; ma++) {
        #pragma unroll
        for (int na = 0; na < 8; na++) {
            int col = n0 + na * 8 + cpair;
            float bx = bsm[col], by = bsm[col + 1];
            #pragma unroll
            for (int half = 0; half < 2; half++) {
                int r = rbase + ma * 16 + half * 8;
                if (r < rows) {
                    float v0 = acc[ma][na][half * 2]     + bx;
                    float v1 = acc[ma][na][half * 2 + 1] + by;
                    float2 o;
                    o.x = (v0 >= 0.f) ? v0 : 0.01f * v0;
                    o.y = (v1 >= 0.f) ? v1 : 0.01f * v1;
                    *(float2*)(Out + (size_t)(block_row + r) * D + col) = o;
                }
            }
        }
    }
}

// ---------------- launch ----------------
extern "C" void kernel_launch(void* const* d_in, const int* in_sizes, int n_in,
                              void* d_out, int out_size) {
    const float* feat = (const float*)d_in[0];
    const int*   ei32 = (const int*)d_in[1];   // int32 OR int64 (auto-detected)
    const float* W1   = (const float*)d_in[2];
    const float* b1   = (const float*)d_in[3];
    const float* W2   = (const float*)d_in[4];
    const float* b2   = (const float*)d_in[5];
    float* out = (float*)d_out;

    int N = in_sizes[0] / D;      // 100000
    int E = in_sizes[1] / 2;      // 1600000

    cudaFuncSetAttribute(gemm_mma_kernel,
                         cudaFuncAttributeMaxDynamicSharedMemorySize, SM_TOT);

    // dtype detection + CSR build (shared by both layers)
    detect_kernel<<<1, 32>>>(ei32);
    zero_deg_kernel<<<(N + 255) / 256, 256>>>(N);
    count_kernel<<<(E + 255) / 256, 256>>>(ei32, E);
    scan_local_kernel<<<SCAN_NBLK, 1024>>>(N);
    scan_bsum_kernel<<<1, 32>>>(SCAN_NBLK);
    scan_add_kernel<<<SCAN_NBLK, 1024>>>(N);
    fill_kernel<<<(E + 255) / 256, 256>>>(ei32, E);

    int agg_blocks  = (N + 7) / 8;
    int gemm_blocks = (N + 127) / 128;

    // layer 1
    convert_w_kernel<<<64, 256>>>(W1);
    aggregate_kernel<<<agg_blocks, 256>>>(feat, N);
    gemm_mma_kernel<<<gemm_blocks, 256, SM_TOT>>>(b1, out, N);
    // layer 2
    convert_w_kernel<<<64, 256>>>(W2);
    aggregate_kernel<<<agg_blocks, 256>>>(out, N);
    gemm_mma_kernel<<<gemm_blocks, 256, SM_TOT>>>(b2, out, N);
}

// round 9
// speedup vs baseline: 1.9671x; 1.1743x over previous
#include <cuda_runtime.h>
#include <cuda_bf16.h>
#include <cuda_fp16.h>
#include <cstdint>

#define NN 100000
#define NE 1600000
#define D  128
#define SCAN_CHUNK 2048
#define SCAN_NBLK ((NN + SCAN_CHUNK - 1) / SCAN_CHUNK)   // 49

// ---------------- scratch: __device__ globals only ----------------
__device__ int   g_is64;
__device__ int   g_deg[NN];
__device__ int   g_off[NN];
__device__ int   g_cursor[NN];
__device__ int   g_bsum[SCAN_NBLK];
__device__ int   g_srcs[NE];
__device__ __half g_xh[(size_t)NN * D];           // gather table (fp16)
__device__ __nv_bfloat16 g_ahi[(size_t)NN * D];   // aggregated feats, bf16 hi
__device__ __nv_bfloat16 g_alo[(size_t)NN * D];   // bf16 lo residual
__device__ __nv_bfloat16 g_bhi[D * D];            // W^T hi  [n][k]
__device__ __nv_bfloat16 g_blo[D * D];            // W^T lo  [n][k]

// ---------------- warp-MMA helpers (sm_80+ features, safe on sm_103 target) ----
__device__ __forceinline__ uint32_t smem_u32(const void* p) {
    uint32_t a;
    asm("{ .reg .u64 t; cvta.to.shared.u64 t, %1; cvt.u32.u64 %0, t; }"
        : "=r"(a) : "l"(p));
    return a;
}
__device__ __forceinline__ void ldsm_x4(uint32_t* r, uint32_t addr) {
    asm volatile("ldmatrix.sync.aligned.m8n8.x4.shared.b16 {%0,%1,%2,%3}, [%4];"
                 : "=r"(r[0]), "=r"(r[1]), "=r"(r[2]), "=r"(r[3]) : "r"(addr));
}
__device__ __forceinline__ void mma_bf16(float* c, const uint32_t* a,
                                         const uint32_t* b) {
    asm volatile(
        "mma.sync.aligned.m16n8k16.row.col.f32.bf16.bf16.f32 "
        "{%0,%1,%2,%3}, {%4,%5,%6,%7}, {%8,%9}, {%0,%1,%2,%3};"
        : "+f"(c[0]), "+f"(c[1]), "+f"(c[2]), "+f"(c[3])
        : "r"(a[0]), "r"(a[1]), "r"(a[2]), "r"(a[3]), "r"(b[0]), "r"(b[1]));
}

// ---------------- dtype detection ----------------
__global__ void detect_kernel(const int* __restrict__ ei32) {
    if (blockIdx.x == 0 && threadIdx.x == 0) {
        int nz = 0;
        #pragma unroll 8
        for (int i = 0; i < 512; i++) nz |= ei32[2 * i + 1];
        g_is64 = (nz == 0) ? 1 : 0;
    }
}

// ---------------- CSR build ----------------
__global__ void zero_deg_kernel(int n) {
    int i = blockIdx.x * blockDim.x + threadIdx.x;
    if (i < n) g_deg[i] = 0;
}
__device__ __forceinline__ int load_idx(const int* __restrict__ ei32,
                                        int is64, size_t pos) {
    return is64 ? ei32[2 * pos] : ei32[pos];
}
__global__ void count_kernel(const int* __restrict__ ei32, int E) {
    int e = blockIdx.x * blockDim.x + threadIdx.x;
    if (e < E) {
        int dst = load_idx(ei32, g_is64, (size_t)E + e);
        if ((unsigned)dst < (unsigned)NN) atomicAdd(&g_deg[dst], 1);
    }
}

__global__ __launch_bounds__(1024)
void scan_local_kernel(int n) {
    __shared__ int wsum[32];
    int t = threadIdx.x, lane = t & 31, w = t >> 5;
    int base = blockIdx.x * SCAN_CHUNK;
    int i0 = base + 2 * t, i1 = i0 + 1;
    int v0 = (i0 < n) ? g_deg[i0] : 0;
    int v1 = (i1 < n) ? g_deg[i1] : 0;
    int s = v0 + v1;
    int inc = s;
    #pragma unroll
    for (int d = 1; d < 32; d <<= 1) {
        int nb = __shfl_up_sync(0xffffffffu, inc, d);
        if (lane >= d) inc += nb;
    }
    if (lane == 31) wsum[w] = inc;
    __syncthreads();
    if (w == 0) {
        int x = wsum[lane];
        #pragma unroll
        for (int d = 1; d < 32; d <<= 1) {
            int nb = __shfl_up_sync(0xffffffffu, x, d);
            if (lane >= d) x += nb;
        }
        wsum[lane] = x;
    }
    __syncthreads();
    int woff = (w == 0) ? 0 : wsum[w - 1];
    int exc = woff + inc - s;
    if (i0 < n) g_off[i0] = exc;
    if (i1 < n) g_off[i1] = exc + v0;
    if (t == 1023) g_bsum[blockIdx.x] = wsum[31];   // single writer
}

__global__ void scan_bsum_kernel(int nb) {
    int lane = threadIdx.x;
    int v0 = (lane < nb) ? g_bsum[lane] : 0;
    int v1 = (lane + 32 < nb) ? g_bsum[lane + 32] : 0;
    int s0 = v0;
    #pragma unroll
    for (int d = 1; d < 32; d <<= 1) {
        int nb_ = __shfl_up_sync(0xffffffffu, s0, d);
        if (lane >= d) s0 += nb_;
    }
    int tot0 = __shfl_sync(0xffffffffu, s0, 31);
    int s1 = v1;
    #pragma unroll
    for (int d = 1; d < 32; d <<= 1) {
        int nb_ = __shfl_up_sync(0xffffffffu, s1, d);
        if (lane >= d) s1 += nb_;
    }
    s1 += tot0;
    if (lane < nb)      g_bsum[lane]      = s0 - v0;
    if (lane + 32 < nb) g_bsum[lane + 32] = s1 - v1;
}

__global__ __launch_bounds__(1024)
void scan_add_kernel(int n) {
    int add = g_bsum[blockIdx.x];
    int base = blockIdx.x * SCAN_CHUNK;
    int i0 = base + 2 * threadIdx.x, i1 = i0 + 1;
    if (i0 < n) { int o = g_off[i0] + add; g_off[i0] = o; g_cursor[i0] = o; }
    if (i1 < n) { int o = g_off[i1] + add; g_off[i1] = o; g_cursor[i1] = o; }
}

__global__ void fill_kernel(const int* __restrict__ ei32, int E) {
    int e = blockIdx.x * blockDim.x + threadIdx.x;
    if (e < E) {
        int is64 = g_is64;
        int src = load_idx(ei32, is64, (size_t)e);
        int dst = load_idx(ei32, is64, (size_t)E + e);
        if ((unsigned)dst < (unsigned)NN && (unsigned)src < (unsigned)NN) {
            int pos = atomicAdd(&g_cursor[dst], 1);
            if ((unsigned)pos < (unsigned)NE) g_srcs[pos] = src;
        }
    }
}

// ---------------- feat fp32 -> fp16 gather table ----------------
__global__ void convert_feat_kernel(const float* __restrict__ X, int total4) {
    int i = blockIdx.x * blockDim.x + threadIdx.x;   // one float4 per thread
    if (i < total4) {
        float4 v = ((const float4*)X)[i];
        __half2 a = __floats2half2_rn(v.x, v.y);
        __half2 b = __floats2half2_rn(v.z, v.w);
        ((__half2*)g_xh)[2 * i]     = a;
        ((__half2*)g_xh)[2 * i + 1] = b;
    }
}

// ---------------- aggregation: warp per node, fp16 gather, fp32 accumulate ------
__global__ void aggregate_kernel(int n) {
    int node = blockIdx.x * (blockDim.x >> 5) + (threadIdx.x >> 5);
    int lane = threadIdx.x & 31;
    if (node >= n) return;
    int start = g_off[node];
    int cnt   = g_deg[node];
    const uint2* X2 = (const uint2*)g_xh;   // 4 halves per uint2; 32 uint2 per row

    float acc0 = 0.f, acc1 = 0.f, acc2 = 0.f, acc3 = 0.f;
    int e = 0;
    for (; e + 4 <= cnt; e += 4) {
        int s0 = g_srcs[start + e + 0];
        int s1 = g_srcs[start + e + 1];
        int s2 = g_srcs[start + e + 2];
        int s3 = g_srcs[start + e + 3];
        uint2 v0 = __ldg(X2 + (size_t)s0 * 32 + lane);
        uint2 v1 = __ldg(X2 + (size_t)s1 * 32 + lane);
        uint2 v2 = __ldg(X2 + (size_t)s2 * 32 + lane);
        uint2 v3 = __ldg(X2 + (size_t)s3 * 32 + lane);
        #pragma unroll
        for (int q = 0; q < 4; q++) {
            uint2 v = (q == 0) ? v0 : (q == 1) ? v1 : (q == 2) ? v2 : v3;
            float2 f01 = __half22float2(*(__half2*)&v.x);
            float2 f23 = __half22float2(*(__half2*)&v.y);
            acc0 += f01.x; acc1 += f01.y; acc2 += f23.x; acc3 += f23.y;
        }
    }
    for (; e < cnt; e++) {
        int s = g_srcs[start + e];
        uint2 v = __ldg(X2 + (size_t)s * 32 + lane);
        float2 f01 = __half22float2(*(__half2*)&v.x);
        float2 f23 = __half22float2(*(__half2*)&v.y);
        acc0 += f01.x; acc1 += f01.y; acc2 += f23.x; acc3 += f23.y;
    }
    {
        uint2 v = __ldg(X2 + (size_t)node * 32 + lane);
        float2 f01 = __half22float2(*(__half2*)&v.x);
        float2 f23 = __half22float2(*(__half2*)&v.y);
        acc0 += f01.x; acc1 += f01.y; acc2 += f23.x; acc3 += f23.y;
    }
    float inv = 1.0f / (float)(cnt + 1);
    float h[4] = {acc0 * inv, acc1 * inv, acc2 * inv, acc3 * inv};

    __nv_bfloat16 hi[4], lo[4];
    #pragma unroll
    for (int i = 0; i < 4; i++) {
        hi[i] = __float2bfloat16_rn(h[i]);
        lo[i] = __float2bfloat16_rn(h[i] - __bfloat162float(hi[i]));
    }
    size_t base = (size_t)node * D + lane * 4;
    *(__nv_bfloat162*)(g_ahi + base)     = __nv_bfloat162(hi[0], hi[1]);
    *(__nv_bfloat162*)(g_ahi + base + 2) = __nv_bfloat162(hi[2], hi[3]);
    *(__nv_bfloat162*)(g_alo + base)     = __nv_bfloat162(lo[0], lo[1]);
    *(__nv_bfloat162*)(g_alo + base + 2) = __nv_bfloat162(lo[2], lo[3]);
}

// ---------------- W -> W^T bf16 hi/lo ----------------
__global__ void convert_w_kernel(const float* __restrict__ W) {
    int idx = blockIdx.x * blockDim.x + threadIdx.x;
    if (idx >= D * D) return;
    int n = idx >> 7, k = idx & 127;
    float x = W[k * D + n];
    __nv_bfloat16 hi = __float2bfloat16_rn(x);
    __nv_bfloat16 lo = __float2bfloat16_rn(x - __bfloat162float(hi));
    g_bhi[n * D + k] = hi;
    g_blo[n * D + k] = lo;
}

// ---------------- warp-MMA bf16-split GEMM + bias + leaky relu ----------------
// block: 256 threads (8 warps), tile M=128 N=128 K=128.
// warp w: m0 = (w&3)*32, n0 = (w>>2)*64. 3 MMA terms: Ahi*Bhi + Ahi*Blo + Alo*Bhi.
// write_fp16 != 0 -> write activations as fp16 into g_xh (layer 1)
// write_fp16 == 0 -> write fp32 into Out (layer 2 / final)
#define ROWB 272
#define SM_BIAS 0
#define SM_AHI  512
#define SM_ALO  (SM_AHI + 128 * ROWB)
#define SM_BHI  (SM_ALO + 128 * ROWB)
#define SM_BLO  (SM_BHI + 128 * ROWB)
#define SM_TOT  (SM_BLO + 128 * ROWB)   // 139776 B

__global__ __launch_bounds__(256)
void gemm_mma_kernel(const float* __restrict__ bias,
                     float* __restrict__ Out, int write_fp16, int M) {
    extern __shared__ char smem[];
    uint32_t sb = smem_u32(smem);
    int t = threadIdx.x, lane = t & 31, wid = t >> 5;

    int block_row = blockIdx.x * 128;
    int rows = M - block_row; if (rows > 128) rows = 128;

    if (t < 32) *(float4*)(smem + SM_BIAS + t * 16) = ((const float4*)bias)[t];

    {
        const uint4 z4 = make_uint4(0, 0, 0, 0);
        #pragma unroll
        for (int it = 0; it < 8; it++) {
            int i = t + it * 256;
            int r = i >> 4, c = i & 15;
            uint32_t so = r * ROWB + c * 16;
            size_t g = (size_t)r * 16 + c;
            uint4 va = z4, vl = z4;
            if (r < rows) {
                size_t ga = ((size_t)(block_row + r) * 16) + c;
                va = ((const uint4*)g_ahi)[ga];
                vl = ((const uint4*)g_alo)[ga];
            }
            *(uint4*)(smem + SM_AHI + so) = va;
            *(uint4*)(smem + SM_ALO + so) = vl;
            *(uint4*)(smem + SM_BHI + so) = ((const uint4*)g_bhi)[g];
            *(uint4*)(smem + SM_BLO + so) = ((const uint4*)g_blo)[g];
        }
    }
    __syncthreads();

    int m0 = (wid & 3) * 32;
    int n0 = (wid >> 2) * 64;

    float acc[2][8][4];
    #pragma unroll
    for (int ma = 0; ma < 2; ma++)
        #pragma unroll
        for (int na = 0; na < 8; na++)
            #pragma unroll
            for (int q = 0; q < 4; q++) acc[ma][na][q] = 0.f;

    uint32_t aAddr[2];
    #pragma unroll
    for (int ma = 0; ma < 2; ma++) {
        int r = m0 + ma * 16 + (lane & 15);
        aAddr[ma] = sb + SM_AHI + r * ROWB + (lane >> 4) * 16;
    }
    uint32_t bAddr[4];
    {
        int q = lane >> 3;
        int nrow_off = ((q & 2) << 2) + (lane & 7);
        int kadd = (q & 1) * 8;
        #pragma unroll
        for (int p = 0; p < 4; p++) {
            int nrow = n0 + p * 16 + nrow_off;
            bAddr[p] = sb + SM_BHI + nrow * ROWB + kadd * 2;
        }
    }
    const uint32_t ALO_OFF = SM_ALO - SM_AHI;
    const uint32_t BLO_OFF = SM_BLO - SM_BHI;

    #pragma unroll
    for (int ks = 0; ks < 8; ks++) {
        uint32_t kb = ks * 32;
        uint32_t ahi[2][4], alo[2][4], bhi[8][2], blo[8][2];
        #pragma unroll
        for (int ma = 0; ma < 2; ma++) {
            ldsm_x4(ahi[ma], aAddr[ma] + kb);
            ldsm_x4(alo[ma], aAddr[ma] + ALO_OFF + kb);
        }
        #pragma unroll
        for (int p = 0; p < 4; p++) {
            uint32_t rh[4], rl[4];
            ldsm_x4(rh, bAddr[p] + kb);
            ldsm_x4(rl, bAddr[p] + BLO_OFF + kb);
            bhi[2 * p][0] = rh[0]; bhi[2 * p][1] = rh[1];
            bhi[2 * p + 1][0] = rh[2]; bhi[2 * p + 1][1] = rh[3];
            blo[2 * p][0] = rl[0]; blo[2 * p][1] = rl[1];
            blo[2 * p + 1][0] = rl[2]; blo[2 * p + 1][1] = rl[3];
        }
        #pragma unroll
        for (int ma = 0; ma < 2; ma++)
            #pragma unroll
            for (int na = 0; na < 8; na++) {
                mma_bf16(acc[ma][na], ahi[ma], bhi[na]);
                mma_bf16(acc[ma][na], ahi[ma], blo[na]);
                mma_bf16(acc[ma][na], alo[ma], bhi[na]);
            }
    }

    const float* bsm = (const float*)(smem + SM_BIAS);
    int rbase = m0 + (lane >> 2);
    int cpair = (lane & 3) * 2;
    #pragma unroll
    for (int ma = 0; ma < 2; ma++) {
        #pragma unroll
        for (int na = 0; na < 8; na++) {
            int col = n0 + na * 8 + cpair;
            float bx = bsm[col], by = bsm[col + 1];
            #pragma unroll
            for (int half = 0; half < 2; half++) {
                int r = rbase + ma * 16 + half * 8;
                if (r < rows) {
                    float v0 = acc[ma][na][half * 2]     + bx;
                    float v1 = acc[ma][na][half * 2 + 1] + by;
                    float o0 = (v0 >= 0.f) ? v0 : 0.01f * v0;
                    float o1 = (v1 >= 0.f) ? v1 : 0.01f * v1;
                    size_t idx = (size_t)(block_row + r) * D + col;
                    if (write_fp16) {
                        *(__half2*)(g_xh + idx) = __floats2half2_rn(o0, o1);
                    } else {
                        *(float2*)(Out + idx) = make_float2(o0, o1);
                    }
                }
            }
        }
    }
}

// ---------------- launch ----------------
extern "C" void kernel_launch(void* const* d_in, const int* in_sizes, int n_in,
                              void* d_out, int out_size) {
    const float* feat = (const float*)d_in[0];
    const int*   ei32 = (const int*)d_in[1];   // int32 OR int64 (auto-detected)
    const float* W1   = (const float*)d_in[2];
    const float* b1   = (const float*)d_in[3];
    const float* W2   = (const float*)d_in[4];
    const float* b2   = (const float*)d_in[5];
    float* out = (float*)d_out;

    int N = in_sizes[0] / D;      // 100000
    int E = in_sizes[1] / 2;      // 1600000

    cudaFuncSetAttribute(gemm_mma_kernel,
                         cudaFuncAttributeMaxDynamicSharedMemorySize, SM_TOT);

    // dtype detection + CSR build (shared by both layers)
    detect_kernel<<<1, 32>>>(ei32);
    zero_deg_kernel<<<(N + 255) / 256, 256>>>(N);
    count_kernel<<<(E + 255) / 256, 256>>>(ei32, E);
    scan_local_kernel<<<SCAN_NBLK, 1024>>>(N);
    scan_bsum_kernel<<<1, 32>>>(SCAN_NBLK);
    scan_add_kernel<<<SCAN_NBLK, 1024>>>(N);
    fill_kernel<<<(E + 255) / 256, 256>>>(ei32, E);

    int agg_blocks  = (N + 7) / 8;
    int gemm_blocks = (N + 127) / 128;
    int total4      = N * D / 4;

    // layer 1: feat->fp16 table, aggregate, GEMM (writes fp16 activations to g_xh)
    convert_w_kernel<<<64, 256>>>(W1);
    convert_feat_kernel<<<(total4 + 255) / 256, 256>>>(feat, total4);
    aggregate_kernel<<<agg_blocks, 256>>>(N);
    gemm_mma_kernel<<<gemm_blocks, 256, SM_TOT>>>(b1, out, 1, N);
    // layer 2: aggregate fp16 activations, GEMM -> fp32 d_out
    convert_w_kernel<<<64, 256>>>(W2);
    aggregate_kernel<<<agg_blocks, 256>>>(N);
    gemm_mma_kernel<<<gemm_blocks, 256, SM_TOT>>>(b2, out, 0, N);
}

// round 10
// speedup vs baseline: 2.3914x; 1.2157x over previous
#include <cuda_runtime.h>
#include <cuda_fp16.h>
#include <cstdint>

#define NN 100000
#define NE 1600000
#define D  128
#define SCAN_CHUNK 2048
#define SCAN_NBLK ((NN + SCAN_CHUNK - 1) / SCAN_CHUNK)   // 49

// ---------------- scratch: __device__ globals only ----------------
__device__ int   g_is64;
__device__ int   g_deg[NN];
__device__ int   g_off[NN];
__device__ int   g_cursor[NN];
__device__ int   g_bsum[SCAN_NBLK];
__device__ int   g_srcs[NE];
__device__ __half g_xh[(size_t)NN * D];   // gather table (fp16): feat, then layer-1 acts
__device__ __half g_ah[(size_t)NN * D];   // aggregated+normalized features (GEMM A, fp16)
__device__ __half g_bh[D * D];            // W^T fp16  [n][k]

// ---------------- warp-MMA helpers (sm_80+ features, safe on sm_103 target) ----
__device__ __forceinline__ uint32_t smem_u32(const void* p) {
    uint32_t a;
    asm("{ .reg .u64 t; cvta.to.shared.u64 t, %1; cvt.u32.u64 %0, t; }"
        : "=r"(a) : "l"(p));
    return a;
}
__device__ __forceinline__ void ldsm_x4(uint32_t* r, uint32_t addr) {
    asm volatile("ldmatrix.sync.aligned.m8n8.x4.shared.b16 {%0,%1,%2,%3}, [%4];"
                 : "=r"(r[0]), "=r"(r[1]), "=r"(r[2]), "=r"(r[3]) : "r"(addr));
}
__device__ __forceinline__ void mma_fp16(float* c, const uint32_t* a,
                                         const uint32_t* b) {
    asm volatile(
        "mma.sync.aligned.m16n8k16.row.col.f32.f16.f16.f32 "
        "{%0,%1,%2,%3}, {%4,%5,%6,%7}, {%8,%9}, {%0,%1,%2,%3};"
        : "+f"(c[0]), "+f"(c[1]), "+f"(c[2]), "+f"(c[3])
        : "r"(a[0]), "r"(a[1]), "r"(a[2]), "r"(a[3]), "r"(b[0]), "r"(b[1]));
}

// ---------------- dtype detection ----------------
__global__ void detect_kernel(const int* __restrict__ ei32) {
    if (blockIdx.x == 0 && threadIdx.x == 0) {
        int nz = 0;
        #pragma unroll 8
        for (int i = 0; i < 512; i++) nz |= ei32[2 * i + 1];
        g_is64 = (nz == 0) ? 1 : 0;
    }
}

// ---------------- CSR build ----------------
__global__ void zero_deg_kernel(int n) {
    int i = blockIdx.x * blockDim.x + threadIdx.x;
    if (i < n) g_deg[i] = 0;
}
__device__ __forceinline__ int load_idx(const int* __restrict__ ei32,
                                        int is64, size_t pos) {
    return is64 ? ei32[2 * pos] : ei32[pos];
}
__global__ void count_kernel(const int* __restrict__ ei32, int E) {
    int e = blockIdx.x * blockDim.x + threadIdx.x;
    if (e < E) {
        int dst = load_idx(ei32, g_is64, (size_t)E + e);
        if ((unsigned)dst < (unsigned)NN) atomicAdd(&g_deg[dst], 1);
    }
}

__global__ __launch_bounds__(1024)
void scan_local_kernel(int n) {
    __shared__ int wsum[32];
    int t = threadIdx.x, lane = t & 31, w = t >> 5;
    int base = blockIdx.x * SCAN_CHUNK;
    int i0 = base + 2 * t, i1 = i0 + 1;
    int v0 = (i0 < n) ? g_deg[i0] : 0;
    int v1 = (i1 < n) ? g_deg[i1] : 0;
    int s = v0 + v1;
    int inc = s;
    #pragma unroll
    for (int d = 1; d < 32; d <<= 1) {
        int nb = __shfl_up_sync(0xffffffffu, inc, d);
        if (lane >= d) inc += nb;
    }
    if (lane == 31) wsum[w] = inc;
    __syncthreads();
    if (w == 0) {
        int x = wsum[lane];
        #pragma unroll
        for (int d = 1; d < 32; d <<= 1) {
            int nb = __shfl_up_sync(0xffffffffu, x, d);
            if (lane >= d) x += nb;
        }
        wsum[lane] = x;
    }
    __syncthreads();
    int woff = (w == 0) ? 0 : wsum[w - 1];
    int exc = woff + inc - s;
    if (i0 < n) g_off[i0] = exc;
    if (i1 < n) g_off[i1] = exc + v0;
    if (t == 1023) g_bsum[blockIdx.x] = wsum[31];   // single writer
}

__global__ void scan_bsum_kernel(int nb) {
    int lane = threadIdx.x;
    int v0 = (lane < nb) ? g_bsum[lane] : 0;
    int v1 = (lane + 32 < nb) ? g_bsum[lane + 32] : 0;
    int s0 = v0;
    #pragma unroll
    for (int d = 1; d < 32; d <<= 1) {
        int nb_ = __shfl_up_sync(0xffffffffu, s0, d);
        if (lane >= d) s0 += nb_;
    }
    int tot0 = __shfl_sync(0xffffffffu, s0, 31);
    int s1 = v1;
    #pragma unroll
    for (int d = 1; d < 32; d <<= 1) {
        int nb_ = __shfl_up_sync(0xffffffffu, s1, d);
        if (lane >= d) s1 += nb_;
    }
    s1 += tot0;
    if (lane < nb)      g_bsum[lane]      = s0 - v0;
    if (lane + 32 < nb) g_bsum[lane + 32] = s1 - v1;
}

__global__ __launch_bounds__(1024)
void scan_add_kernel(int n) {
    int add = g_bsum[blockIdx.x];
    int base = blockIdx.x * SCAN_CHUNK;
    int i0 = base + 2 * threadIdx.x, i1 = i0 + 1;
    if (i0 < n) { int o = g_off[i0] + add; g_off[i0] = o; g_cursor[i0] = o; }
    if (i1 < n) { int o = g_off[i1] + add; g_off[i1] = o; g_cursor[i1] = o; }
}

__global__ void fill_kernel(const int* __restrict__ ei32, int E) {
    int e = blockIdx.x * blockDim.x + threadIdx.x;
    if (e < E) {
        int is64 = g_is64;
        int src = load_idx(ei32, is64, (size_t)e);
        int dst = load_idx(ei32, is64, (size_t)E + e);
        if ((unsigned)dst < (unsigned)NN && (unsigned)src < (unsigned)NN) {
            int pos = atomicAdd(&g_cursor[dst], 1);
            if ((unsigned)pos < (unsigned)NE) g_srcs[pos] = src;
        }
    }
}

// ---------------- feat fp32 -> fp16 gather table ----------------
__global__ void convert_feat_kernel(const float* __restrict__ X, int total4) {
    int i = blockIdx.x * blockDim.x + threadIdx.x;   // one float4 per thread
    if (i < total4) {
        float4 v = ((const float4*)X)[i];
        ((__half2*)g_xh)[2 * i]     = __floats2half2_rn(v.x, v.y);
        ((__half2*)g_xh)[2 * i + 1] = __floats2half2_rn(v.z, v.w);
    }
}

// ---------------- aggregation: warp per node, fp16 gather, fp32 accumulate ------
__global__ void aggregate_kernel(int n) {
    int node = blockIdx.x * (blockDim.x >> 5) + (threadIdx.x >> 5);
    int lane = threadIdx.x & 31;
    if (node >= n) return;
    int start = g_off[node];
    int cnt   = g_deg[node];
    const uint2* X2 = (const uint2*)g_xh;   // 4 halves per uint2; 32 uint2 per row

    float acc0 = 0.f, acc1 = 0.f, acc2 = 0.f, acc3 = 0.f;
    int e = 0;
    for (; e + 4 <= cnt; e += 4) {
        int s0 = g_srcs[start + e + 0];
        int s1 = g_srcs[start + e + 1];
        int s2 = g_srcs[start + e + 2];
        int s3 = g_srcs[start + e + 3];
        uint2 v0 = __ldg(X2 + (size_t)s0 * 32 + lane);
        uint2 v1 = __ldg(X2 + (size_t)s1 * 32 + lane);
        uint2 v2 = __ldg(X2 + (size_t)s2 * 32 + lane);
        uint2 v3 = __ldg(X2 + (size_t)s3 * 32 + lane);
        #pragma unroll
        for (int q = 0; q < 4; q++) {
            uint2 v = (q == 0) ? v0 : (q == 1) ? v1 : (q == 2) ? v2 : v3;
            float2 f01 = __half22float2(*(__half2*)&v.x);
            float2 f23 = __half22float2(*(__half2*)&v.y);
            acc0 += f01.x; acc1 += f01.y; acc2 += f23.x; acc3 += f23.y;
        }
    }
    for (; e < cnt; e++) {
        int s = g_srcs[start + e];
        uint2 v = __ldg(X2 + (size_t)s * 32 + lane);
        float2 f01 = __half22float2(*(__half2*)&v.x);
        float2 f23 = __half22float2(*(__half2*)&v.y);
        acc0 += f01.x; acc1 += f01.y; acc2 += f23.x; acc3 += f23.y;
    }
    {
        uint2 v = __ldg(X2 + (size_t)node * 32 + lane);
        float2 f01 = __half22float2(*(__half2*)&v.x);
        float2 f23 = __half22float2(*(__half2*)&v.y);
        acc0 += f01.x; acc1 += f01.y; acc2 += f23.x; acc3 += f23.y;
    }
    float inv = 1.0f / (float)(cnt + 1);
    size_t base = (size_t)node * D + lane * 4;
    *(__half2*)(g_ah + base)     = __floats2half2_rn(acc0 * inv, acc1 * inv);
    *(__half2*)(g_ah + base + 2) = __floats2half2_rn(acc2 * inv, acc3 * inv);
}

// ---------------- W -> W^T fp16 ----------------
__global__ void convert_w_kernel(const float* __restrict__ W) {
    int idx = blockIdx.x * blockDim.x + threadIdx.x;
    if (idx >= D * D) return;
    int n = idx >> 7, k = idx & 127;
    g_bh[n * D + k] = __float2half_rn(W[k * D + n]);
}

// ---------------- warp-MMA fp16 GEMM + bias + leaky relu ----------------
// block: 256 threads (8 warps), tile M=128 N=128 K=128.
// warp w: m0 = (w&3)*32, n0 = (w>>2)*64. Single term: A(fp16) * W^T(fp16), fp32 acc.
// write_fp16 != 0 -> write activations as fp16 into g_xh (layer 1)
// write_fp16 == 0 -> write fp32 into Out (layer 2 / final)
#define ROWB 272                     // padded row: 136 fp16 = 272 B (conflict-free ldsm)
#define SM_BIAS 0
#define SM_A  512
#define SM_B  (SM_A + 128 * ROWB)
#define SM_TOT (SM_B + 128 * ROWB)   // 70144 B

__global__ __launch_bounds__(256)
void gemm_mma_kernel(const float* __restrict__ bias,
                     float* __restrict__ Out, int write_fp16, int M) {
    extern __shared__ char smem[];
    uint32_t sb = smem_u32(smem);
    int t = threadIdx.x, lane = t & 31, wid = t >> 5;

    int block_row = blockIdx.x * 128;
    int rows = M - block_row; if (rows > 128) rows = 128;

    if (t < 32) *(float4*)(smem + SM_BIAS + t * 16) = ((const float4*)bias)[t];

    // stage A and B tiles: row r (128), 16B chunk c (16)
    {
        const uint4 z4 = make_uint4(0, 0, 0, 0);
        #pragma unroll
        for (int it = 0; it < 8; it++) {
            int i = t + it * 256;
            int r = i >> 4, c = i & 15;
            uint32_t so = r * ROWB + c * 16;
            uint4 va = z4;
            if (r < rows)
                va = ((const uint4*)g_ah)[((size_t)(block_row + r) * 16) + c];
            *(uint4*)(smem + SM_A + so) = va;
            *(uint4*)(smem + SM_B + so) = ((const uint4*)g_bh)[(size_t)r * 16 + c];
        }
    }
    __syncthreads();

    int m0 = (wid & 3) * 32;
    int n0 = (wid >> 2) * 64;

    float acc[2][8][4];
    #pragma unroll
    for (int ma = 0; ma < 2; ma++)
        #pragma unroll
        for (int na = 0; na < 8; na++)
            #pragma unroll
            for (int q = 0; q < 4; q++) acc[ma][na][q] = 0.f;

    // per-lane ldmatrix base addresses (k-step adds 32 B)
    uint32_t aAddr[2];
    #pragma unroll
    for (int ma = 0; ma < 2; ma++) {
        int r = m0 + ma * 16 + (lane & 15);
        aAddr[ma] = sb + SM_A + r * ROWB + (lane >> 4) * 16;
    }
    uint32_t bAddr[4];
    {
        int q = lane >> 3;
        int nrow_off = ((q & 2) << 2) + (lane & 7);
        int kadd = (q & 1) * 8;
        #pragma unroll
        for (int p = 0; p < 4; p++) {
            int nrow = n0 + p * 16 + nrow_off;
            bAddr[p] = sb + SM_B + nrow * ROWB + kadd * 2;
        }
    }

    #pragma unroll
    for (int ks = 0; ks < 8; ks++) {
        uint32_t kb = ks * 32;
        uint32_t a[2][4], b[8][2];
        #pragma unroll
        for (int ma = 0; ma < 2; ma++)
            ldsm_x4(a[ma], aAddr[ma] + kb);
        #pragma unroll
        for (int p = 0; p < 4; p++) {
            uint32_t rh[4];
            ldsm_x4(rh, bAddr[p] + kb);
            b[2 * p][0] = rh[0]; b[2 * p][1] = rh[1];
            b[2 * p + 1][0] = rh[2]; b[2 * p + 1][1] = rh[3];
        }
        #pragma unroll
        for (int ma = 0; ma < 2; ma++)
            #pragma unroll
            for (int na = 0; na < 8; na++)
                mma_fp16(acc[ma][na], a[ma], b[na]);
    }

    // epilogue: D frag lane l -> rows l/4 (+8), cols (l%4)*2,+1
    const float* bsm = (const float*)(smem + SM_BIAS);
    int rbase = m0 + (lane >> 2);
    int cpair = (lane & 3) * 2;
    #pragma unroll
    for (int ma = 0; ma < 2; ma++) {
        #pragma unroll
        for (int na = 0; na < 8; na++) {
            int col = n0 + na * 8 + cpair;
            float bx = bsm[col], by = bsm[col + 1];
            #pragma unroll
            for (int half = 0; half < 2; half++) {
                int r = rbase + ma * 16 + half * 8;
                if (r < rows) {
                    float v0 = acc[ma][na][half * 2]     + bx;
                    float v1 = acc[ma][na][half * 2 + 1] + by;
                    float o0 = (v0 >= 0.f) ? v0 : 0.01f * v0;
                    float o1 = (v1 >= 0.f) ? v1 : 0.01f * v1;
                    size_t idx = (size_t)(block_row + r) * D + col;
                    if (write_fp16) {
                        *(__half2*)(g_xh + idx) = __floats2half2_rn(o0, o1);
                    } else {
                        *(float2*)(Out + idx) = make_float2(o0, o1);
                    }
                }
            }
        }
    }
}

// ---------------- launch ----------------
extern "C" void kernel_launch(void* const* d_in, const int* in_sizes, int n_in,
                              void* d_out, int out_size) {
    const float* feat = (const float*)d_in[0];
    const int*   ei32 = (const int*)d_in[1];   // int32 OR int64 (auto-detected)
    const float* W1   = (const float*)d_in[2];
    const float* b1   = (const float*)d_in[3];
    const float* W2   = (const float*)d_in[4];
    const float* b2   = (const float*)d_in[5];
    float* out = (float*)d_out;

    int N = in_sizes[0] / D;      // 100000
    int E = in_sizes[1] / 2;      // 1600000

    cudaFuncSetAttribute(gemm_mma_kernel,
                         cudaFuncAttributeMaxDynamicSharedMemorySize, SM_TOT);

    // dtype detection + CSR build (shared by both layers)
    detect_kernel<<<1, 32>>>(ei32);
    zero_deg_kernel<<<(N + 255) / 256, 256>>>(N);
    count_kernel<<<(E + 255) / 256, 256>>>(ei32, E);
    scan_local_kernel<<<SCAN_NBLK, 1024>>>(N);
    scan_bsum_kernel<<<1, 32>>>(SCAN_NBLK);
    scan_add_kernel<<<SCAN_NBLK, 1024>>>(N);
    fill_kernel<<<(E + 255) / 256, 256>>>(ei32, E);

    int agg_blocks  = (N + 7) / 8;
    int gemm_blocks = (N + 127) / 128;
    int total4      = N * D / 4;

    // layer 1: feat->fp16 table, aggregate, GEMM (writes fp16 activations to g_xh)
    convert_w_kernel<<<64, 256>>>(W1);
    convert_feat_kernel<<<(total4 + 255) / 256, 256>>>(feat, total4);
    aggregate_kernel<<<agg_blocks, 256>>>(N);
    gemm_mma_kernel<<<gemm_blocks, 256, SM_TOT>>>(b1, out, 1, N);
    // layer 2: aggregate fp16 activations, GEMM -> fp32 d_out
    convert_w_kernel<<<64, 256>>>(W2);
    aggregate_kernel<<<agg_blocks, 256>>>(N);
    gemm_mma_kernel<<<gemm_blocks, 256, SM_TOT>>>(b2, out, 0, N);
}